// round 4
// baseline (speedup 1.0000x reference)
#include <cuda_runtime.h>
#include <cuda_fp16.h>

#define TSTEPS 2048
#define HID    2048
#define INP    1024
#define NOUT   512
#define ZLEN   (HID + INP)
#define NCTA   148
#define JPER   14

// SMEM layout for recurrent kernel
#define SMEM_W_BYTES (JPER * 4 * HID * 2)          /* 229376 */
#define SMEM_PART_OFF (SMEM_W_BYTES)               /* 64 floats */
#define SMEM_G_OFF   (SMEM_W_BYTES + 256)          /* 2 x 64 floats */
#define SMEM_TOTAL   (SMEM_W_BYTES + 256 + 512)    /* 230144 */

// Scratch: device globals (allowed; no runtime allocation)
__device__ float    d_G[(size_t)4 * HID * TSTEPS]; // 64MB preactivations [r][t], r = g*H + j
__device__ unsigned d_bar;                         // grid barrier counter (reset via memset node)

// ---------------------------------------------------------------------------
// helpers
// ---------------------------------------------------------------------------
__device__ __forceinline__ unsigned long long pack_u64(unsigned lo, unsigned hi) {
    unsigned long long r;
    asm("mov.b64 %0, {%1, %2};" : "=l"(r) : "r"(lo), "r"(hi));
    return r;
}

// acc(f32x2) += cvt_f32x2(w half2) * h(f32x2)
__device__ __forceinline__ void cvt_fma2(unsigned long long &acc, unsigned w2,
                                         unsigned long long h2) {
    asm("{\n\t"
        ".reg .f16 wl, wh;\n\t"
        ".reg .f32 fl, fh;\n\t"
        ".reg .b64 wp;\n\t"
        "mov.b32 {wl, wh}, %1;\n\t"
        "cvt.f32.f16 fl, wl;\n\t"
        "cvt.f32.f16 fh, wh;\n\t"
        "mov.b64 wp, {fl, fh};\n\t"
        "fma.rn.f32x2 %0, wp, %2, %0;\n\t"
        "}"
        : "+l"(acc) : "r"(w2), "l"(h2));
}

__device__ __forceinline__ float unpack_sum(unsigned long long a) {
    float lo, hi;
    asm("mov.b64 {%0, %1}, %2;" : "=f"(lo), "=f"(hi) : "l"(a));
    return lo + hi;
}

__device__ __forceinline__ float sigmoidf_(float x) {
    return 1.0f / (1.0f + __expf(-x));
}
__device__ __forceinline__ float tanhf_(float x) {
    float e = __expf(2.0f * x);
    return 1.0f - 2.0f / (e + 1.0f);   // safe at +/- inf
}

// ---------------------------------------------------------------------------
// 1) G[r][t] = sum_k W_g[j][H+k] * X[t][k] + b_g[j]    (r = g*H + j)
//    128x128 tile, k-tile 16, 256 threads, 8x8 microtile
// ---------------------------------------------------------------------------
__global__ __launch_bounds__(256) void gemm_xpart(
    const float* __restrict__ Wf, const float* __restrict__ Wi,
    const float* __restrict__ Wc, const float* __restrict__ Wo,
    const float* __restrict__ bf, const float* __restrict__ bi,
    const float* __restrict__ bc, const float* __restrict__ bo,
    const float* __restrict__ X)
{
    __shared__ float As[16][132];
    __shared__ float Bs[16][132];
    const int bx = blockIdx.x;              // t tile (0..15)
    const int by = blockIdx.y;              // row tile (0..63)
    const int g  = by >> 4;
    const int jb = (by & 15) << 7;
    const float* W  = (g == 0) ? Wf : (g == 1) ? Wi : (g == 2) ? Wc : Wo;
    const float* bb = (g == 0) ? bf : (g == 1) ? bi : (g == 2) ? bc : bo;
    const int tid = threadIdx.x;
    const int tx = tid & 15, ty = tid >> 4;

    float acc[8][8];
#pragma unroll
    for (int i = 0; i < 8; ++i)
#pragma unroll
        for (int j = 0; j < 8; ++j) acc[i][j] = 0.0f;

    for (int k0 = 0; k0 < INP; k0 += 16) {
#pragma unroll
        for (int i = 0; i < 2; ++i) {
            int f   = tid + i * 256;
            int row = f >> 2;
            int kk  = (f & 3) << 2;
            float4 v = *(const float4*)(W + (size_t)(jb + row) * ZLEN + HID + k0 + kk);
            As[kk + 0][row] = v.x; As[kk + 1][row] = v.y;
            As[kk + 2][row] = v.z; As[kk + 3][row] = v.w;
            float4 u = *(const float4*)(X + (size_t)((bx << 7) + row) * INP + k0 + kk);
            Bs[kk + 0][row] = u.x; Bs[kk + 1][row] = u.y;
            Bs[kk + 2][row] = u.z; Bs[kk + 3][row] = u.w;
        }
        __syncthreads();
#pragma unroll
        for (int k = 0; k < 16; ++k) {
            float a[8], b[8];
            *(float4*)&a[0] = *(const float4*)&As[k][ty * 8];
            *(float4*)&a[4] = *(const float4*)&As[k][ty * 8 + 4];
            *(float4*)&b[0] = *(const float4*)&Bs[k][tx * 8];
            *(float4*)&b[4] = *(const float4*)&Bs[k][tx * 8 + 4];
#pragma unroll
            for (int ii = 0; ii < 8; ++ii)
#pragma unroll
                for (int jj = 0; jj < 8; ++jj)
                    acc[ii][jj] = fmaf(a[ii], b[jj], acc[ii][jj]);
        }
        __syncthreads();
    }
#pragma unroll
    for (int ii = 0; ii < 8; ++ii) {
        const int r   = (by << 7) + ty * 8 + ii;
        const float bv = __ldg(bb + jb + ty * 8 + ii);
        float4 s0, s1;
        s0.x = acc[ii][0] + bv; s0.y = acc[ii][1] + bv;
        s0.z = acc[ii][2] + bv; s0.w = acc[ii][3] + bv;
        s1.x = acc[ii][4] + bv; s1.y = acc[ii][5] + bv;
        s1.z = acc[ii][6] + bv; s1.w = acc[ii][7] + bv;
        float* dst = d_G + (size_t)r * TSTEPS + (bx << 7) + tx * 8;
        *(float4*)dst       = s0;
        *(float4*)(dst + 4) = s1;
    }
}

// ---------------------------------------------------------------------------
// 2) Persistent recurrent kernel. 148 CTAs x 1024 threads.
//    Warps 0..27 : 2 gate dots each (jj = w>>1, gates (w&1)*2 + {0,1})
//    Warp  28    : state finalize (c,h) + grid barrier
//    Warps 29,30 : y GEMV for previous step (overlapped)
//    Warp  31    : G prefetch for next step
// ---------------------------------------------------------------------------
__global__ void __launch_bounds__(1024, 1) lstm_recurrent(
    const float* __restrict__ Wf, const float* __restrict__ Wi,
    const float* __restrict__ Wc, const float* __restrict__ Wo,
    const float* __restrict__ Wy, const float* __restrict__ by,
    float* __restrict__ out)
{
    extern __shared__ char smem_raw[];
    __half* sW   = (__half*)smem_raw;
    float* sPart = (float*)(smem_raw + SMEM_PART_OFF);
    float* sG    = (float*)(smem_raw + SMEM_G_OFF);     // sG[2][64]

    const int tid  = threadIdx.x;
    const int wid  = tid >> 5;
    const int lane = tid & 31;
    const int bid  = blockIdx.x;
    const int jb   = bid * JPER;
    int njj = HID - jb;
    njj = njj < 0 ? 0 : (njj > JPER ? JPER : njj);

    float* out_y = out;
    float* out_h = out + (size_t)TSTEPS * NOUT;

    // ---- load + convert this CTA's recurrent weights into SMEM (fp16) ----
    {
        const int nchunk = njj * 4 * (HID / 4);          // chunks of 4 floats
        for (int c = tid; c < nchunk; c += 1024) {
            int jj = c >> 11;                            // 2048 chunks per jj
            int g  = (c >> 9) & 3;
            int k4 = (c & 511) << 2;
            const float* W = (g == 0) ? Wf : (g == 1) ? Wi : (g == 2) ? Wc : Wo;
            float4 v = *(const float4*)(W + (size_t)(jb + jj) * ZLEN + k4);
            union { __half2 h2[2]; uint2 u; } cv;
            cv.h2[0] = __floats2half2_rn(v.x, v.y);
            cv.h2[1] = __floats2half2_rn(v.z, v.w);
            *(uint2*)(sW + ((jj * 4 + g) * HID + k4)) = cv.u;
        }
    }

    // ---- preload G for t = 0 into buffer 0 ----
    if (wid == 31) {
        for (int i = lane; i < 56; i += 32) {
            int jj = i >> 2, g = i & 3;
            float v = 0.0f;
            if (jj < njj) v = __ldg(&d_G[((size_t)(g * HID + jb + jj)) * TSTEPS]);
            sG[i] = v;
        }
    }
    __syncthreads();

    // per-role persistent registers
    float c_st = 0.0f;                                   // warp 28, lane = jj
    float by0 = 0.0f, by1 = 0.0f;
    int   r0  = 0;
    const bool doY = (bid < 128);
    if ((wid == 29 || wid == 30) && doY) {
        r0  = bid * 4 + (wid - 29) * 2;
        by0 = __ldg(by + r0);
        by1 = __ldg(by + r0 + 1);
    }

    for (int t = 0; t <= TSTEPS; ++t) {
        if (wid < 28) {
            if (t < TSTEPS) {
                const int jj = wid >> 1;
                const int g0 = (wid & 1) * 2;
                float p0 = 0.0f, p1 = 0.0f;
                if (jj < njj && t > 0) {
                    const __half* w0 = sW + (jj * 4 + g0) * HID + lane * 4;
                    const __half* w1 = w0 + HID;
                    const float* hsrc = out_h + (size_t)(t - 1) * HID + lane * 4;
                    unsigned long long a0 = 0, a1 = 0, b0 = 0, b1 = 0;
#pragma unroll 4
                    for (int kk = 0; kk < 16; ++kk) {
                        uint4 hv = __ldcg((const uint4*)(hsrc + kk * 128));
                        unsigned long long hlo = pack_u64(hv.x, hv.y);
                        unsigned long long hhi = pack_u64(hv.z, hv.w);
                        uint2 wa = *(const uint2*)(w0 + kk * 128);
                        uint2 wb = *(const uint2*)(w1 + kk * 128);
                        cvt_fma2(a0, wa.x, hlo);
                        cvt_fma2(a1, wa.y, hhi);
                        cvt_fma2(b0, wb.x, hlo);
                        cvt_fma2(b1, wb.y, hhi);
                    }
                    p0 = unpack_sum(a0) + unpack_sum(a1);
                    p1 = unpack_sum(b0) + unpack_sum(b1);
#pragma unroll
                    for (int off = 16; off > 0; off >>= 1) {
                        p0 += __shfl_xor_sync(0xFFFFFFFFu, p0, off);
                        p1 += __shfl_xor_sync(0xFFFFFFFFu, p1, off);
                    }
                }
                if (lane == 0 && jj < njj) {
                    const float* gb = sG + (t & 1) * 64 + jj * 4 + g0;
                    sPart[jj * 4 + g0]     = p0 + gb[0];
                    sPart[jj * 4 + g0 + 1] = p1 + gb[1];
                }
                asm volatile("bar.sync 1, 928;" ::: "memory");
            }
        } else if (wid == 28) {
            if (t < TSTEPS) {
                asm volatile("bar.sync 1, 928;" ::: "memory");
                if (lane < njj) {
                    float4 p = *(const float4*)(sPart + lane * 4);
                    float fg = sigmoidf_(p.x);
                    float ig = sigmoidf_(p.y);
                    float cc = tanhf_(p.z);
                    float og = sigmoidf_(p.w);
                    c_st = fg * c_st + ig * cc;
                    float hv = og * tanhf_(c_st);
                    out_h[(size_t)t * HID + jb + lane] = hv;
                }
                __threadfence();
                if (lane == 0) {
                    atomicAdd(&d_bar, 1u);
                    const unsigned target = (unsigned)(t + 1) * gridDim.x;
                    while (*(volatile unsigned*)&d_bar < target) { }
                }
            }
        } else if (wid == 29 || wid == 30) {
            if (t >= 1 && doY) {
                const float* hsrc = out_h + (size_t)(t - 1) * HID + lane * 4;
                const float* wy0  = Wy + (size_t)r0 * HID + lane * 4;
                const float* wy1  = wy0 + HID;
                float s0 = 0.0f, s1 = 0.0f;
#pragma unroll 4
                for (int kk = 0; kk < 16; ++kk) {
                    float4 hv  = __ldcg((const float4*)(hsrc + kk * 128));
                    float4 w0v = __ldg((const float4*)(wy0 + kk * 128));
                    float4 w1v = __ldg((const float4*)(wy1 + kk * 128));
                    s0 = fmaf(w0v.x, hv.x, s0); s0 = fmaf(w0v.y, hv.y, s0);
                    s0 = fmaf(w0v.z, hv.z, s0); s0 = fmaf(w0v.w, hv.w, s0);
                    s1 = fmaf(w1v.x, hv.x, s1); s1 = fmaf(w1v.y, hv.y, s1);
                    s1 = fmaf(w1v.z, hv.z, s1); s1 = fmaf(w1v.w, hv.w, s1);
                }
#pragma unroll
                for (int off = 16; off > 0; off >>= 1) {
                    s0 += __shfl_xor_sync(0xFFFFFFFFu, s0, off);
                    s1 += __shfl_xor_sync(0xFFFFFFFFu, s1, off);
                }
                if (lane == 0) {
                    out_y[(size_t)(t - 1) * NOUT + r0]     = s0 + by0;
                    out_y[(size_t)(t - 1) * NOUT + r0 + 1] = s1 + by1;
                }
            }
        } else { // wid == 31: prefetch G for step t+1
            if (t + 1 < TSTEPS) {
                for (int i = lane; i < 56; i += 32) {
                    int jj = i >> 2, g = i & 3;
                    float v = 0.0f;
                    if (jj < njj)
                        v = __ldg(&d_G[((size_t)(g * HID + jb + jj)) * TSTEPS + (t + 1)]);
                    sG[((t + 1) & 1) * 64 + i] = v;
                }
            }
        }
        if (t < TSTEPS) __syncthreads();
    }
}

// ---------------------------------------------------------------------------
// launch
// ---------------------------------------------------------------------------
extern "C" void kernel_launch(void* const* d_in, const int* in_sizes, int n_in,
                              void* d_out, int out_size) {
    (void)in_sizes; (void)n_in; (void)out_size;
    const float* X  = (const float*)d_in[0];
    const float* Wf = (const float*)d_in[1];
    const float* bf = (const float*)d_in[2];
    const float* Wi = (const float*)d_in[3];
    const float* bi = (const float*)d_in[4];
    const float* Wc = (const float*)d_in[5];
    const float* bc = (const float*)d_in[6];
    const float* Wo = (const float*)d_in[7];
    const float* bo = (const float*)d_in[8];
    const float* Wy = (const float*)d_in[9];
    const float* by = (const float*)d_in[10];
    float* out = (float*)d_out;

    cudaFuncSetAttribute(lstm_recurrent,
                         cudaFuncAttributeMaxDynamicSharedMemorySize, SMEM_TOTAL);

    void* barp = nullptr;
    cudaGetSymbolAddress(&barp, d_bar);
    cudaMemsetAsync(barp, 0, sizeof(unsigned), 0);

    gemm_xpart<<<dim3(16, 64), 256>>>(Wf, Wi, Wc, Wo, bf, bi, bc, bo, X);
    lstm_recurrent<<<NCTA, 1024, SMEM_TOTAL>>>(Wf, Wi, Wc, Wo, Wy, by, out);
}

// round 5
// speedup vs baseline: 2.0369x; 2.0369x over previous
#include <cuda_runtime.h>
#include <cuda_fp16.h>

#define TSTEPS 2048
#define HID    2048
#define INP    1024
#define NOUT   512
#define ZLEN   (HID + INP)
#define NCTA   148
#define JPER   14
#define KS     1920                                   /* k-values per row in SMEM */

#define SW_BYTES   (56 * KS * 2)                      /* 215040 */
#define SH_OFF     SW_BYTES                           /* 8192 B: h(t-1) fp32 */
#define SPART_OFF  (SW_BYTES + 8192)                  /* 256 B */
#define SG_OFF     (SW_BYTES + 8192 + 256)            /* 512 B */
#define SMEM_TOTAL (SW_BYTES + 8192 + 256 + 512)      /* 223999 -> 224000 */

__device__ float    d_G[(size_t)4 * HID * TSTEPS];    // [r][t], r = g*HID + j
__device__ unsigned d_bar;

__device__ __forceinline__ unsigned long long pack_u64(unsigned lo, unsigned hi) {
    unsigned long long r;
    asm("mov.b64 %0, {%1, %2};" : "=l"(r) : "r"(lo), "r"(hi));
    return r;
}
__device__ __forceinline__ void cvt_fma2(unsigned long long &acc, unsigned w2,
                                         unsigned long long h2) {
    asm("{\n\t"
        ".reg .f16 wl, wh;\n\t.reg .f32 fl, fh;\n\t.reg .b64 wp;\n\t"
        "mov.b32 {wl, wh}, %1;\n\t"
        "cvt.f32.f16 fl, wl;\n\tcvt.f32.f16 fh, wh;\n\t"
        "mov.b64 wp, {fl, fh};\n\t"
        "fma.rn.f32x2 %0, wp, %2, %0;\n\t}"
        : "+l"(acc) : "r"(w2), "l"(h2));
}
__device__ __forceinline__ float unpack_sum(unsigned long long a) {
    float lo, hi;
    asm("mov.b64 {%0, %1}, %2;" : "=f"(lo), "=f"(hi) : "l"(a));
    return lo + hi;
}
__device__ __forceinline__ unsigned packh2(float a, float b) {
    __half2 h = __floats2half2_rn(a, b);
    return *(unsigned*)&h;
}
__device__ __forceinline__ float sigmoidf_(float x) { return 1.0f / (1.0f + __expf(-x)); }
__device__ __forceinline__ float tanhf_(float x) {
    float e = __expf(2.0f * x); return 1.0f - 2.0f / (e + 1.0f);
}

// ---------------- GEMM for x-part preactivations (unchanged, proven) ----------
__global__ __launch_bounds__(256) void gemm_xpart(
    const float* __restrict__ Wf, const float* __restrict__ Wi,
    const float* __restrict__ Wc, const float* __restrict__ Wo,
    const float* __restrict__ bf, const float* __restrict__ bi,
    const float* __restrict__ bc, const float* __restrict__ bo,
    const float* __restrict__ X)
{
    __shared__ float As[16][132];
    __shared__ float Bs[16][132];
    const int bx = blockIdx.x, by = blockIdx.y;
    const int g = by >> 4, jb = (by & 15) << 7;
    const float* W  = (g == 0) ? Wf : (g == 1) ? Wi : (g == 2) ? Wc : Wo;
    const float* bb = (g == 0) ? bf : (g == 1) ? bi : (g == 2) ? bc : bo;
    const int tid = threadIdx.x, tx = tid & 15, ty = tid >> 4;
    float acc[8][8];
#pragma unroll
    for (int i = 0; i < 8; ++i)
#pragma unroll
        for (int j = 0; j < 8; ++j) acc[i][j] = 0.0f;
    for (int k0 = 0; k0 < INP; k0 += 16) {
#pragma unroll
        for (int i = 0; i < 2; ++i) {
            int f = tid + i * 256, row = f >> 2, kk = (f & 3) << 2;
            float4 v = *(const float4*)(W + (size_t)(jb + row) * ZLEN + HID + k0 + kk);
            As[kk][row] = v.x; As[kk+1][row] = v.y; As[kk+2][row] = v.z; As[kk+3][row] = v.w;
            float4 u = *(const float4*)(X + (size_t)((bx << 7) + row) * INP + k0 + kk);
            Bs[kk][row] = u.x; Bs[kk+1][row] = u.y; Bs[kk+2][row] = u.z; Bs[kk+3][row] = u.w;
        }
        __syncthreads();
#pragma unroll
        for (int k = 0; k < 16; ++k) {
            float a[8], b[8];
            *(float4*)&a[0] = *(const float4*)&As[k][ty*8];
            *(float4*)&a[4] = *(const float4*)&As[k][ty*8+4];
            *(float4*)&b[0] = *(const float4*)&Bs[k][tx*8];
            *(float4*)&b[4] = *(const float4*)&Bs[k][tx*8+4];
#pragma unroll
            for (int ii = 0; ii < 8; ++ii)
#pragma unroll
                for (int jj = 0; jj < 8; ++jj)
                    acc[ii][jj] = fmaf(a[ii], b[jj], acc[ii][jj]);
        }
        __syncthreads();
    }
#pragma unroll
    for (int ii = 0; ii < 8; ++ii) {
        const int r = (by << 7) + ty*8 + ii;
        const float bv = __ldg(bb + jb + ty*8 + ii);
        float4 s0 = {acc[ii][0]+bv, acc[ii][1]+bv, acc[ii][2]+bv, acc[ii][3]+bv};
        float4 s1 = {acc[ii][4]+bv, acc[ii][5]+bv, acc[ii][6]+bv, acc[ii][7]+bv};
        float* dst = d_G + (size_t)r * TSTEPS + (bx << 7) + tx*8;
        *(float4*)dst = s0; *(float4*)(dst + 4) = s1;
    }
}

// ---------------- persistent recurrent kernel --------------------------------
__global__ void __launch_bounds__(1024, 1) lstm_recurrent(
    const float* __restrict__ Wf, const float* __restrict__ Wi,
    const float* __restrict__ Wc, const float* __restrict__ Wo,
    const float* __restrict__ Wy, const float* __restrict__ by,
    float* __restrict__ out)
{
    extern __shared__ char smem[];
    __half* sW   = (__half*)smem;
    float*  sH   = (float*)(smem + SH_OFF);
    float*  sPart= (float*)(smem + SPART_OFF);
    float*  sG   = (float*)(smem + SG_OFF);

    const int tid = threadIdx.x, wid = tid >> 5, lane = tid & 31;
    const int bid = blockIdx.x, jb = bid * JPER;
    int njj = HID - jb; njj = njj < 0 ? 0 : (njj > JPER ? JPER : njj);
    float* out_y = out;
    float* out_h = out + (size_t)TSTEPS * NOUT;
    unsigned* barp = &d_bar;

    // weights (k < KS) -> SMEM fp16
    for (int c = tid; c < 56 * (KS / 4); c += 1024) {
        int row = c / (KS / 4);
        int kq  = (c - row * (KS / 4)) * 4;
        int jj = row >> 2, g = row & 3;
        const float* W = (g == 0) ? Wf : (g == 1) ? Wi : (g == 2) ? Wc : Wo;
        uint2 u = {0u, 0u};
        if (jj < njj) {
            float4 v = *(const float4*)(W + (size_t)(jb + jj) * ZLEN + kq);
            u.x = packh2(v.x, v.y); u.y = packh2(v.z, v.w);
        }
        *(uint2*)(sW + row * KS + kq) = u;
    }

    // weight tail (k = KS..2047) -> registers in gate warps
    unsigned wr0x = 0, wr0y = 0, wr1x = 0, wr1y = 0;
    if (wid < 28) {
        int jj = wid >> 1, g0 = (wid & 1) * 2;
        if (jj < njj) {
            const float* W0 = (g0 == 0) ? Wf : Wc;     // g0 in {0,2}
            const float* W1 = (g0 == 0) ? Wi : Wo;     // g0+1 in {1,3}
            float4 v = *(const float4*)(W0 + (size_t)(jb + jj) * ZLEN + KS + lane * 4);
            wr0x = packh2(v.x, v.y); wr0y = packh2(v.z, v.w);
            v = *(const float4*)(W1 + (size_t)(jb + jj) * ZLEN + KS + lane * 4);
            wr1x = packh2(v.x, v.y); wr1y = packh2(v.z, v.w);
        }
    }

    // preload G(t=0) into buffer 0
    if (wid == 31) {
        for (int i = lane; i < 56; i += 32) {
            int jj = i >> 2, g = i & 3;
            sG[i] = (jj < njj) ? __ldg(&d_G[((size_t)(g * HID + jb + jj)) * TSTEPS]) : 0.0f;
        }
    }

    float c_st = 0.0f;
    float by0 = 0.0f, by1 = 0.0f;
    int   r0 = 0;
    const bool doY = (bid < 128);
    if ((wid == 29 || wid == 30) && doY) {
        r0 = bid * 4 + (wid - 29) * 2;
        by0 = __ldg(by + r0); by1 = __ldg(by + r0 + 1);
    }
    __syncthreads();

    for (int t = 0; t <= TSTEPS; ++t) {
        // wait until all CTAs' h(t-1) is globally visible
        if (t > 0 && wid == 28 && lane == 0) {
            const unsigned target = (unsigned)t * (unsigned)gridDim.x;
            unsigned v;
            do {
                asm volatile("ld.acquire.gpu.global.u32 %0, [%1];"
                             : "=r"(v) : "l"(barp) : "memory");
            } while (v < target);
        }
        __syncthreads();                               // S1

        // stage h(t-1) -> sH (fp32), warps 0..7
        if (wid < 8) {
            float4 h0 = {0,0,0,0}, h1 = {0,0,0,0};
            if (t > 0) {
                const float* hp = out_h + (size_t)(t - 1) * HID + tid * 8;
                h0 = __ldcg((const float4*)hp);
                h1 = __ldcg((const float4*)(hp + 4));
            }
            *(float4*)(sH + tid * 8)     = h0;
            *(float4*)(sH + tid * 8 + 4) = h1;
        }
        __syncthreads();                               // S2

        if (t < TSTEPS) {
            if (wid < 28) {
                const int jj = wid >> 1, g0 = (wid & 1) * 2;
                const __half* w0 = sW + (jj * 4 + g0) * KS;
                const __half* w1 = w0 + KS;
                unsigned long long a0 = 0, a1 = 0, b0 = 0, b1 = 0;
#pragma unroll
                for (int kk = 0; kk < 15; ++kk) {
                    uint4 hv = ((const uint4*)sH)[kk * 32 + lane];
                    unsigned long long hlo = pack_u64(hv.x, hv.y);
                    unsigned long long hhi = pack_u64(hv.z, hv.w);
                    uint2 wa = ((const uint2*)w0)[kk * 32 + lane];
                    uint2 wb = ((const uint2*)w1)[kk * 32 + lane];
                    cvt_fma2(a0, wa.x, hlo); cvt_fma2(a1, wa.y, hhi);
                    cvt_fma2(b0, wb.x, hlo); cvt_fma2(b1, wb.y, hhi);
                }
                {   // register tail, k = KS + lane*4
                    uint4 hv = ((const uint4*)sH)[480 + lane];
                    unsigned long long hlo = pack_u64(hv.x, hv.y);
                    unsigned long long hhi = pack_u64(hv.z, hv.w);
                    cvt_fma2(a0, wr0x, hlo); cvt_fma2(a1, wr0y, hhi);
                    cvt_fma2(b0, wr1x, hlo); cvt_fma2(b1, wr1y, hhi);
                }
                float p0 = unpack_sum(a0) + unpack_sum(a1);
                float p1 = unpack_sum(b0) + unpack_sum(b1);
#pragma unroll
                for (int off = 16; off > 0; off >>= 1) {
                    p0 += __shfl_xor_sync(0xFFFFFFFFu, p0, off);
                    p1 += __shfl_xor_sync(0xFFFFFFFFu, p1, off);
                }
                if (lane == 0 && jj < njj) {
                    const float* gb = sG + (t & 1) * 64 + jj * 4 + g0;
                    sPart[jj * 4 + g0]     = p0 + gb[0];
                    sPart[jj * 4 + g0 + 1] = p1 + gb[1];
                }
                asm volatile("bar.sync 1, 928;" ::: "memory");
            } else if (wid == 28) {
                asm volatile("bar.sync 1, 928;" ::: "memory");
                if (lane < njj) {
                    float4 p = *(const float4*)(sPart + lane * 4);
                    float fg = sigmoidf_(p.x);
                    float ig = sigmoidf_(p.y);
                    float cc = tanhf_(p.z);
                    float og = sigmoidf_(p.w);
                    c_st = fg * c_st + ig * cc;
                    out_h[(size_t)t * HID + jb + lane] = og * tanhf_(c_st);
                }
                __threadfence();
                if (lane == 0)
                    asm volatile("red.global.add.u32 [%0], %1;" :: "l"(barp), "r"(1u) : "memory");
            } else if (wid == 29 || wid == 30) {
                if (t >= 1 && doY) {
                    const float* wy0 = Wy + (size_t)r0 * HID + lane * 4;
                    const float* wy1 = wy0 + HID;
                    float s0 = 0.0f, s1 = 0.0f;
#pragma unroll 4
                    for (int kk = 0; kk < 16; ++kk) {
                        float4 hv  = *(const float4*)(sH + kk * 128 + lane * 4);
                        float4 w0v = __ldg((const float4*)(wy0 + kk * 128));
                        float4 w1v = __ldg((const float4*)(wy1 + kk * 128));
                        s0 = fmaf(w0v.x, hv.x, s0); s0 = fmaf(w0v.y, hv.y, s0);
                        s0 = fmaf(w0v.z, hv.z, s0); s0 = fmaf(w0v.w, hv.w, s0);
                        s1 = fmaf(w1v.x, hv.x, s1); s1 = fmaf(w1v.y, hv.y, s1);
                        s1 = fmaf(w1v.z, hv.z, s1); s1 = fmaf(w1v.w, hv.w, s1);
                    }
#pragma unroll
                    for (int off = 16; off > 0; off >>= 1) {
                        s0 += __shfl_xor_sync(0xFFFFFFFFu, s0, off);
                        s1 += __shfl_xor_sync(0xFFFFFFFFu, s1, off);
                    }
                    if (lane == 0) {
                        out_y[(size_t)(t - 1) * NOUT + r0]     = s0 + by0;
                        out_y[(size_t)(t - 1) * NOUT + r0 + 1] = s1 + by1;
                    }
                }
            } else { // wid 31: prefetch G(t+1)
                if (t + 1 < TSTEPS) {
                    for (int i = lane; i < 56; i += 32) {
                        int jj = i >> 2, g = i & 3;
                        sG[((t + 1) & 1) * 64 + i] = (jj < njj)
                            ? __ldg(&d_G[((size_t)(g * HID + jb + jj)) * TSTEPS + (t + 1)])
                            : 0.0f;
                    }
                }
            }
        } else { // t == TSTEPS: final y only
            if ((wid == 29 || wid == 30) && doY) {
                const float* wy0 = Wy + (size_t)r0 * HID + lane * 4;
                const float* wy1 = wy0 + HID;
                float s0 = 0.0f, s1 = 0.0f;
#pragma unroll 4
                for (int kk = 0; kk < 16; ++kk) {
                    float4 hv  = *(const float4*)(sH + kk * 128 + lane * 4);
                    float4 w0v = __ldg((const float4*)(wy0 + kk * 128));
                    float4 w1v = __ldg((const float4*)(wy1 + kk * 128));
                    s0 = fmaf(w0v.x, hv.x, s0); s0 = fmaf(w0v.y, hv.y, s0);
                    s0 = fmaf(w0v.z, hv.z, s0); s0 = fmaf(w0v.w, hv.w, s0);
                    s1 = fmaf(w1v.x, hv.x, s1); s1 = fmaf(w1v.y, hv.y, s1);
                    s1 = fmaf(w1v.z, hv.z, s1); s1 = fmaf(w1v.w, hv.w, s1);
                }
#pragma unroll
                for (int off = 16; off > 0; off >>= 1) {
                    s0 += __shfl_xor_sync(0xFFFFFFFFu, s0, off);
                    s1 += __shfl_xor_sync(0xFFFFFFFFu, s1, off);
                }
                if (lane == 0) {
                    out_y[(size_t)(t - 1) * NOUT + r0]     = s0 + by0;
                    out_y[(size_t)(t - 1) * NOUT + r0 + 1] = s1 + by1;
                }
            }
        }
    }
}

extern "C" void kernel_launch(void* const* d_in, const int* in_sizes, int n_in,
                              void* d_out, int out_size) {
    (void)in_sizes; (void)n_in; (void)out_size;
    const float* X  = (const float*)d_in[0];
    const float* Wf = (const float*)d_in[1];
    const float* bf = (const float*)d_in[2];
    const float* Wi = (const float*)d_in[3];
    const float* bi = (const float*)d_in[4];
    const float* Wc = (const float*)d_in[5];
    const float* bc = (const float*)d_in[6];
    const float* Wo = (const float*)d_in[7];
    const float* bo = (const float*)d_in[8];
    const float* Wy = (const float*)d_in[9];
    const float* by = (const float*)d_in[10];
    float* out = (float*)d_out;

    cudaFuncSetAttribute(lstm_recurrent,
                         cudaFuncAttributeMaxDynamicSharedMemorySize, SMEM_TOTAL);
    void* barp = nullptr;
    cudaGetSymbolAddress(&barp, d_bar);
    cudaMemsetAsync(barp, 0, sizeof(unsigned), 0);

    gemm_xpart<<<dim3(16, 64), 256>>>(Wf, Wi, Wc, Wo, bf, bi, bc, bo, X);
    lstm_recurrent<<<NCTA, 1024, SMEM_TOTAL>>>(Wf, Wi, Wc, Wo, Wy, by, out);
}